// round 16
// baseline (speedup 1.0000x reference)
#include <cuda_runtime.h>
#include <cstdint>

// inverse lifting wavelet: (16,256,128,128) f32 -> (16,64,256,256) f32
//
// Y1[b,c,g,h,w]  = in[b, g*64+c, h, w]
// s_g(h,w)       = M2[g,:] . Y1[b,c,:,h,w]
// Y3_i(h,w)      = M1[i,0]*s0(h,w) + M1[i,1]*s1(h-1,w)
//                + M1[i,2]*s2(h,w-1) + M1[i,3]*s3(h-1,w-1)   (indices wrap)
// out[b,c,2h+p,2w+q] = Y3_{2p+q}(h,w)
//
// R16: maximum-length phase-separated bursts. HT=32 strip fully buffered
// (NSTAGES=33, 66KB dynamic smem/warp, 1 warp per block): halo read-amp
// 33/32 (-8MB reads vs R15), each group-plane burst is 16.5KB contiguous
// (132 LDGSTS, ONE commit, ONE wait), then an uninterrupted 32-row
// compute+store drain. 3 blocks/SM -> 198KB/SM in flight during bursts.
// R14->R15 proved occupancy irrelevant (8.9% occ, 6.11 TB/s); bytes and
// burst contiguity rule.

#define FULL 0xffffffffu

constexpr int H1 = 128, W1 = 128, C = 64;
constexpr int HT = 32;                      // rows per warp strip
constexpr int STAGE_BYTES = 4 * 32 * 16;    // 2048 B per row-stage
constexpr int NSTAGES = HT + 1;             // halo + 32 rows, all buffered
constexpr int SMEM_BYTES = NSTAGES * STAGE_BYTES;  // 67584 B = 66 KB

__device__ __forceinline__ void cpa16(uint32_t saddr, const float* g) {
    asm volatile("cp.async.cg.shared.global [%0], [%1], 16;" :: "r"(saddr), "l"(g));
}
__device__ __forceinline__ void cpa_commit() {
    asm volatile("cp.async.commit_group;");
}
template <int N>
__device__ __forceinline__ void cpa_wait() {
    asm volatile("cp.async.wait_group %0;" :: "n"(N));
}
__device__ __forceinline__ void st4(float* p, float4 v) {
    *(float4*)p = v;                         // default cache policy
}

// Consume prev raw row (pv*) + cur raw row (cv*) -> output rows 2h, 2h+1.
__device__ __forceinline__ void compute_store(
    const float4& pv0, const float4& pv1, const float4& pv2, const float4& pv3,
    const float4& cv0, const float4& cv1, const float4& cv2, const float4& cv3,
    float* __restrict__ outb, int h, int lane)
{
    float cg0[4] = {cv0.x, cv0.y, cv0.z, cv0.w};
    float cg1[4] = {cv1.x, cv1.y, cv1.z, cv1.w};
    float cg2[4] = {cv2.x, cv2.y, cv2.z, cv2.w};
    float cg3[4] = {cv3.x, cv3.y, cv3.z, cv3.w};
    float pg0[4] = {pv0.x, pv0.y, pv0.z, pv0.w};
    float pg1[4] = {pv1.x, pv1.y, pv1.z, pv1.w};
    float pg2[4] = {pv2.x, pv2.y, pv2.z, pv2.w};
    float pg3[4] = {pv3.x, pv3.y, pv3.z, pv3.w};

    float s0[4], s1[4], s2[4], s3[4];
    #pragma unroll
    for (int i = 0; i < 4; ++i) {
        // M2 rows 0,2 on current row; rows 1,3 on previous row
        s0[i] =  1.3968f * cg0[i] - 0.2212f * cg1[i] - 0.5412f * cg2[i] + 1.3066f * cg3[i];
        s2[i] = -0.2212f * cg0[i] - 1.3968f * cg1[i] - 1.3066f * cg2[i] - 0.5412f * cg3[i];
        s1[i] =  0.2212f * pg0[i] + 1.3968f * pg1[i] - 1.3066f * pg2[i] - 0.5412f * pg3[i];
        s3[i] = -1.3968f * pg0[i] + 0.2212f * pg1[i] - 0.5412f * pg2[i] + 1.3066f * pg3[i];
    }

    // w-1 values: circular shift across the warp (implements roll wrap at w=0)
    const int src = (lane + 31) & 31;
    float s2n = __shfl_sync(FULL, s2[3], src);
    float s3n = __shfl_sync(FULL, s3[3], src);
    float a2[4] = {s2n, s2[0], s2[1], s2[2]};
    float a3[4] = {s3n, s3[0], s3[1], s3[2]};

    float* rtop = outb + (size_t)(2 * h)     * 256 + 8 * lane;
    float* rbot = outb + (size_t)(2 * h + 1) * 256 + 8 * lane;

    // top row (Y3_0, Y3_1 interleaved) — compute+store first to cut live regs
    {
        float o0[4], o1[4];
        #pragma unroll
        for (int i = 0; i < 4; ++i) {
            o0[i] =  0.2166f * s0[i] - 0.0256f * s1[i] + 0.1213f * a2[i] + 0.0144f * a3[i];
            o1[i] =  0.0256f * s0[i] + 0.2166f * s1[i] + 0.0144f * a2[i] - 0.1213f * a3[i];
        }
        st4(rtop,     make_float4(o0[0], o1[0], o0[1], o1[1]));
        st4(rtop + 4, make_float4(o0[2], o1[2], o0[3], o1[3]));
    }
    // bottom row (Y3_2, Y3_3 interleaved)
    {
        float o2[4], o3[4];
        #pragma unroll
        for (int i = 0; i < 4; ++i) {
            o2[i] =  0.1213f * s0[i] - 0.0144f * s1[i] - 0.2166f * a2[i] - 0.0256f * a3[i];
            o3[i] = -0.0144f * s0[i] - 0.1213f * s1[i] + 0.0256f * a2[i] - 0.2166f * a3[i];
        }
        st4(rbot,     make_float4(o2[0], o3[0], o2[1], o3[1]));
        st4(rbot + 4, make_float4(o2[2], o3[2], o2[3], o3[3]));
    }
}

__global__ __launch_bounds__(32, 3)
void inlwt_kernel(const float* __restrict__ in, float* __restrict__ out) {
    extern __shared__ __align__(16) char smem[];   // 66 KB dynamic

    const int lane = threadIdx.x & 31;
    const int gw   = blockIdx.x;             // one warp per block, 0..4095

    const int htile = gw & 3;
    const int cc    = (gw >> 2) & 63;
    const int b     = gw >> 8;

    const int h0 = htile * HT;
    const int w0 = lane * 4;

    const float* inb  = in  + (size_t)(b * 256 + cc) * (H1 * W1);
    float*       outb = out + (size_t)(b * C   + cc) * (size_t)(2 * H1) * (2 * W1);
    const size_t gs   = (size_t)64 * H1 * W1;   // channel-group stride

    const uint32_t sbase =
        (uint32_t)__cvta_generic_to_shared(smem) + (uint32_t)(lane * 16);

    // ---- read phase: one g-major burst of 132 LDGSTS, single commit ----
    // stage 0 = halo row (hp), stage s>=1 = row h0+s-1. For htile>0 the 33
    // rows are CONTIGUOUS in memory -> 16.5KB sequential stream per group.
    const int hp = (h0 == 0) ? (H1 - 1) : (h0 - 1);
    #pragma unroll
    for (int g = 0; g < 4; ++g) {
        const float* gp = inb + g * gs + w0;
        #pragma unroll
        for (int s = 0; s < NSTAGES; ++s) {
            const int row = (s == 0) ? hp : (h0 + s - 1);
            cpa16(sbase + s * STAGE_BYTES + g * 512, gp + (size_t)row * W1);
        }
    }
    cpa_commit();
    cpa_wait<0>();                       // whole strip + halo landed

    // read one row-stage into registers (per-lane: reads back its own bytes)
    auto read_stage = [&](int stage, float4& v0, float4& v1, float4& v2, float4& v3) {
        const char* sp = smem + stage * STAGE_BYTES + lane * 16;
        v0 = *(const float4*)(sp + 0 * 512);
        v1 = *(const float4*)(sp + 1 * 512);
        v2 = *(const float4*)(sp + 2 * 512);
        v3 = *(const float4*)(sp + 3 * 512);
    };

    // ---- write phase: uninterrupted 32 row-pair drain ----
    float4 pv0, pv1, pv2, pv3;
    read_stage(0, pv0, pv1, pv2, pv3);

    #pragma unroll 4
    for (int i = 0; i < HT; ++i) {
        float4 cv0, cv1, cv2, cv3;
        read_stage(i + 1, cv0, cv1, cv2, cv3);

        compute_store(pv0, pv1, pv2, pv3, cv0, cv1, cv2, cv3, outb, h0 + i, lane);

        pv0 = cv0; pv1 = cv1; pv2 = cv2; pv3 = cv3;
    }
}

extern "C" void kernel_launch(void* const* d_in, const int* in_sizes, int n_in,
                              void* d_out, int out_size) {
    const float* in = (const float*)d_in[0];
    float* out = (float*)d_out;
    // one-time per-process effect; idempotent and deterministic on every call
    cudaFuncSetAttribute(inlwt_kernel,
                         cudaFuncAttributeMaxDynamicSharedMemorySize, SMEM_BYTES);
    // 16 b * 64 c * 4 htiles = 4096 strips; 1 warp (32 threads) per block.
    inlwt_kernel<<<4096, 32, SMEM_BYTES>>>(in, out);
}

// round 17
// speedup vs baseline: 1.0236x; 1.0236x over previous
#include <cuda_runtime.h>
#include <cstdint>

// inverse lifting wavelet: (16,256,128,128) f32 -> (16,64,256,256) f32
//
// Y1[b,c,g,h,w]  = in[b, g*64+c, h, w]
// s_g(h,w)       = M2[g,:] . Y1[b,c,:,h,w]
// Y3_i(h,w)      = M1[i,0]*s0(h,w) + M1[i,1]*s1(h-1,w)
//                + M1[i,2]*s2(h,w-1) + M1[i,3]*s3(h-1,w-1)   (indices wrap)
// out[b,c,2h+p,2w+q] = Y3_{2p+q}(h,w)
//
// R17: R15 (HT=16 full-buffer burst, the sweet spot: HT=8 and HT=32 both
// lose) with the halo row moved OUT of smem into registers (__ldcs direct
// to pv, latency hidden under the cp.async wait). Smem drops 34KB -> 32KB
// exactly -> 7 blocks/SM instead of 6: +17% warps, 224KB/SM in flight.
// Strip burst stays 8KB contiguous per group-plane (64 LDGSTS, one commit,
// one wait), then uninterrupted 16-row compute+store drain.

#define FULL 0xffffffffu

constexpr int H1 = 128, W1 = 128, C = 64;
constexpr int HT = 16;                      // rows per warp strip
constexpr int STAGE_BYTES = 4 * 32 * 16;    // 2048 B per row-stage
constexpr int NSTAGES = HT;                 // 16 rows; halo lives in regs
constexpr int SMEM_BYTES = NSTAGES * STAGE_BYTES;  // 32768 B = 32 KB

__device__ __forceinline__ void cpa16(uint32_t saddr, const float* g) {
    asm volatile("cp.async.cg.shared.global [%0], [%1], 16;" :: "r"(saddr), "l"(g));
}
__device__ __forceinline__ void cpa_commit() {
    asm volatile("cp.async.commit_group;");
}
template <int N>
__device__ __forceinline__ void cpa_wait() {
    asm volatile("cp.async.wait_group %0;" :: "n"(N));
}
__device__ __forceinline__ void st4(float* p, float4 v) {
    *(float4*)p = v;                         // default cache policy
}
__device__ __forceinline__ float4 ldcs4(const float* p) {
    return __ldcs((const float4*)p);
}

// Consume prev raw row (pv*) + cur raw row (cv*) -> output rows 2h, 2h+1.
__device__ __forceinline__ void compute_store(
    const float4& pv0, const float4& pv1, const float4& pv2, const float4& pv3,
    const float4& cv0, const float4& cv1, const float4& cv2, const float4& cv3,
    float* __restrict__ outb, int h, int lane)
{
    float cg0[4] = {cv0.x, cv0.y, cv0.z, cv0.w};
    float cg1[4] = {cv1.x, cv1.y, cv1.z, cv1.w};
    float cg2[4] = {cv2.x, cv2.y, cv2.z, cv2.w};
    float cg3[4] = {cv3.x, cv3.y, cv3.z, cv3.w};
    float pg0[4] = {pv0.x, pv0.y, pv0.z, pv0.w};
    float pg1[4] = {pv1.x, pv1.y, pv1.z, pv1.w};
    float pg2[4] = {pv2.x, pv2.y, pv2.z, pv2.w};
    float pg3[4] = {pv3.x, pv3.y, pv3.z, pv3.w};

    float s0[4], s1[4], s2[4], s3[4];
    #pragma unroll
    for (int i = 0; i < 4; ++i) {
        // M2 rows 0,2 on current row; rows 1,3 on previous row
        s0[i] =  1.3968f * cg0[i] - 0.2212f * cg1[i] - 0.5412f * cg2[i] + 1.3066f * cg3[i];
        s2[i] = -0.2212f * cg0[i] - 1.3968f * cg1[i] - 1.3066f * cg2[i] - 0.5412f * cg3[i];
        s1[i] =  0.2212f * pg0[i] + 1.3968f * pg1[i] - 1.3066f * pg2[i] - 0.5412f * pg3[i];
        s3[i] = -1.3968f * pg0[i] + 0.2212f * pg1[i] - 0.5412f * pg2[i] + 1.3066f * pg3[i];
    }

    // w-1 values: circular shift across the warp (implements roll wrap at w=0)
    const int src = (lane + 31) & 31;
    float s2n = __shfl_sync(FULL, s2[3], src);
    float s3n = __shfl_sync(FULL, s3[3], src);
    float a2[4] = {s2n, s2[0], s2[1], s2[2]};
    float a3[4] = {s3n, s3[0], s3[1], s3[2]};

    float* rtop = outb + (size_t)(2 * h)     * 256 + 8 * lane;
    float* rbot = outb + (size_t)(2 * h + 1) * 256 + 8 * lane;

    // top row (Y3_0, Y3_1 interleaved) — compute+store first to cut live regs
    {
        float o0[4], o1[4];
        #pragma unroll
        for (int i = 0; i < 4; ++i) {
            o0[i] =  0.2166f * s0[i] - 0.0256f * s1[i] + 0.1213f * a2[i] + 0.0144f * a3[i];
            o1[i] =  0.0256f * s0[i] + 0.2166f * s1[i] + 0.0144f * a2[i] - 0.1213f * a3[i];
        }
        st4(rtop,     make_float4(o0[0], o1[0], o0[1], o1[1]));
        st4(rtop + 4, make_float4(o0[2], o1[2], o0[3], o1[3]));
    }
    // bottom row (Y3_2, Y3_3 interleaved)
    {
        float o2[4], o3[4];
        #pragma unroll
        for (int i = 0; i < 4; ++i) {
            o2[i] =  0.1213f * s0[i] - 0.0144f * s1[i] - 0.2166f * a2[i] - 0.0256f * a3[i];
            o3[i] = -0.0144f * s0[i] - 0.1213f * s1[i] + 0.0256f * a2[i] - 0.2166f * a3[i];
        }
        st4(rbot,     make_float4(o2[0], o3[0], o2[1], o3[1]));
        st4(rbot + 4, make_float4(o2[2], o3[2], o2[3], o3[3]));
    }
}

__global__ __launch_bounds__(32, 7)
void inlwt_kernel(const float* __restrict__ in, float* __restrict__ out) {
    extern __shared__ __align__(16) char smem[];   // 32 KB dynamic

    const int lane = threadIdx.x & 31;
    const int gw   = blockIdx.x;             // one warp per block, 0..8191

    const int htile = gw & 7;
    const int cc    = (gw >> 3) & 63;
    const int b     = gw >> 9;

    const int h0 = htile * HT;
    const int w0 = lane * 4;

    const float* inb  = in  + (size_t)(b * 256 + cc) * (H1 * W1);
    float*       outb = out + (size_t)(b * C   + cc) * (size_t)(2 * H1) * (2 * W1);
    const size_t gs   = (size_t)64 * H1 * W1;   // channel-group stride

    const uint32_t sbase =
        (uint32_t)__cvta_generic_to_shared(smem) + (uint32_t)(lane * 16);

    // ---- read phase ----
    // Halo row -> registers directly (latency hides under the cp.async wait).
    const int hp = (h0 == 0) ? (H1 - 1) : (h0 - 1);
    float4 pv0 = ldcs4(inb + 0 * gs + (size_t)hp * W1 + w0);
    float4 pv1 = ldcs4(inb + 1 * gs + (size_t)hp * W1 + w0);
    float4 pv2 = ldcs4(inb + 2 * gs + (size_t)hp * W1 + w0);
    float4 pv3 = ldcs4(inb + 3 * gs + (size_t)hp * W1 + w0);

    // Strip: one g-major burst of 64 LDGSTS (8KB contiguous per group-plane),
    // single commit, single wait. Stage s = row h0+s.
    #pragma unroll
    for (int g = 0; g < 4; ++g) {
        const float* gp = inb + g * gs + (size_t)h0 * W1 + w0;
        #pragma unroll
        for (int s = 0; s < NSTAGES; ++s)
            cpa16(sbase + s * STAGE_BYTES + g * 512, gp + (size_t)s * W1);
    }
    cpa_commit();
    cpa_wait<0>();                       // whole strip landed

    // read one row-stage into registers (per-lane: reads back its own bytes)
    auto read_stage = [&](int stage, float4& v0, float4& v1, float4& v2, float4& v3) {
        const char* sp = smem + stage * STAGE_BYTES + lane * 16;
        v0 = *(const float4*)(sp + 0 * 512);
        v1 = *(const float4*)(sp + 1 * 512);
        v2 = *(const float4*)(sp + 2 * 512);
        v3 = *(const float4*)(sp + 3 * 512);
    };

    // ---- write phase: uninterrupted 16 row-pair drain ----
    #pragma unroll 4
    for (int i = 0; i < HT; ++i) {
        float4 cv0, cv1, cv2, cv3;
        read_stage(i, cv0, cv1, cv2, cv3);

        compute_store(pv0, pv1, pv2, pv3, cv0, cv1, cv2, cv3, outb, h0 + i, lane);

        pv0 = cv0; pv1 = cv1; pv2 = cv2; pv3 = cv3;
    }
}

extern "C" void kernel_launch(void* const* d_in, const int* in_sizes, int n_in,
                              void* d_out, int out_size) {
    const float* in = (const float*)d_in[0];
    float* out = (float*)d_out;
    // one-time per-process effect; idempotent and deterministic on every call
    cudaFuncSetAttribute(inlwt_kernel,
                         cudaFuncAttributeMaxDynamicSharedMemorySize, SMEM_BYTES);
    // 16 b * 64 c * 8 htiles = 8192 strips; 1 warp (32 threads) per block.
    inlwt_kernel<<<8192, 32, SMEM_BYTES>>>(in, out);
}